// round 6
// baseline (speedup 1.0000x reference)
#include <cuda_runtime.h>
#include <cuda_bf16.h>
#include <cstdint>

#define HCH  512
#define LSEQ 4096
#define TAPS 64

#define NT    256               // 8 warps
#define TCTA  512               // t-positions per CTA (4 tiles of 128)
#define NTILE 4
#define STRW  292               // u32 words per batch strip (288 used + 4 pad)
#define OSTR  132               // floats per output staging row

// Pre-packed A fragments: [h][d][word0..5][lane], words = {hi w0,w1,w2, lo w0,w1,w2}
__device__ uint32_t g_ktab[HCH * 5 * 6 * 32];

__device__ __forceinline__ uint32_t pk_bf2f(float a, float b) {
    __nv_bfloat162 t = __floats2bfloat162_rn(a, b);
    return *reinterpret_cast<uint32_t*>(&t);
}
__device__ __forceinline__ float bflo(uint32_t w) {
    __nv_bfloat162 t = *reinterpret_cast<__nv_bfloat162*>(&w);
    return __bfloat162float(t.x);
}
__device__ __forceinline__ float bfhi(uint32_t w) {
    __nv_bfloat162 t = *reinterpret_cast<__nv_bfloat162*>(&w);
    return __bfloat162float(t.y);
}
__device__ __forceinline__ void mma_bf16(float* d, const uint32_t* a,
                                         uint32_t b0, uint32_t b1) {
    asm volatile(
        "mma.sync.aligned.m16n8k16.row.col.f32.bf16.bf16.f32 "
        "{%0,%1,%2,%3}, {%4,%5,%6,%7}, {%8,%9}, {%0,%1,%2,%3};"
        : "+f"(d[0]), "+f"(d[1]), "+f"(d[2]), "+f"(d[3])
        : "r"(a[0]), "r"(a[1]), "r"(a[2]), "r"(a[3]), "r"(b0), "r"(b1));
}

// ---- prep: K[h,s] = sum_j B[h,j]*C[h,j+s] (+D at s=0); pack A fragments ----
__global__ __launch_bounds__(192) void prep_k(const float* __restrict__ Bp,
                                              const float* __restrict__ Cp,
                                              const float* __restrict__ Dp) {
    __shared__ float sK[TAPS];
    const int h = blockIdx.x;
    const int tid = threadIdx.x;
    if (tid < TAPS) {
        const float* Bh = Bp + h * TAPS;
        const float* Ch = Cp + h * TAPS;
        float a = (tid == 0) ? Dp[h] : 0.0f;
        #pragma unroll
        for (int j = 0; j < TAPS; ++j)
            if (j + tid < TAPS) a = fmaf(Bh[j], Ch[j + tid], a);
        sK[tid] = a;
    }
    __syncthreads();
    if (tid < 160) {
        const int d = tid >> 5, lane = tid & 31;
        const int r = lane >> 2, c0 = (lane & 3) * 2;
        const int s0 = 64 - 16 * d + r - c0;
        const int ss[6] = { s0 + 8, s0 + 7, s0, s0 - 1, s0 - 8, s0 - 9 };
        float f[6];
        #pragma unroll
        for (int q = 0; q < 6; ++q)
            f[q] = (ss[q] >= 0 && ss[q] < TAPS) ? sK[ss[q]] : 0.0f;
        uint32_t w0 = pk_bf2f(f[2], f[3]);
        uint32_t w1 = pk_bf2f(f[0], f[1]);
        uint32_t w2 = pk_bf2f(f[4], f[5]);
        uint32_t l0 = pk_bf2f(f[2] - bflo(w0), f[3] - bfhi(w0));
        uint32_t l1 = pk_bf2f(f[0] - bflo(w1), f[1] - bfhi(w1));
        uint32_t l2 = pk_bf2f(f[4] - bflo(w2), f[5] - bfhi(w2));
        uint32_t* kt = g_ktab + (size_t)((h * 5 + d) * 6) * 32 + lane;
        kt[0]   = w0; kt[32]  = w1; kt[64]  = w2;
        kt[96]  = l0; kt[128] = l1; kt[160] = l2;
    }
}

// ---- conv: banded Toeplitz GEMM, 4 seq-tiles x 8 batches per CTA ----
__global__ __launch_bounds__(NT) void conv_mma(const float* __restrict__ up,
                                               float* __restrict__ yp) {
    __shared__ alignas(16) uint32_t sBuf[2 * 8 * STRW];   // hi strips | lo strips

    const int tid  = threadIdx.x;
    const int wid  = tid >> 5;
    const int lane = tid & 31;
    const int h    = blockIdx.y;
    const int t0   = blockIdx.x * TCTA;

    const float* uh = up + (size_t)h * LSEQ;
    float*       yh = yp + (size_t)h * LSEQ;
    const size_t bstr = (size_t)HCH * LSEQ;

    // A fragments from the prepacked table (coalesced, overlaps im2col)
    uint32_t ah[5][4], al[5][4];
    #pragma unroll
    for (int d = 0; d < 5; ++d) {
        const uint32_t* kt = g_ktab + (size_t)((h * 5 + d) * 6) * 32 + lane;
        uint32_t w0 = kt[0],  w1 = kt[32],  w2 = kt[64];
        uint32_t l0 = kt[96], l1 = kt[128], l2 = kt[160];
        ah[d][0] = w0; ah[d][1] = w1; ah[d][2] = w2; ah[d][3] = w0;
        al[d][0] = l0; al[d][1] = l1; al[d][2] = l2; al[d][3] = l0;
    }

    // im2col: 8 batch strips, t in [t0-64, t0+512), each element converted once
    uint32_t* sBh = sBuf;
    uint32_t* sBl = sBuf + 8 * STRW;
    for (int idx = tid; idx < 8 * 144; idx += NT) {
        int b = idx / 144, q = idx - b * 144;          // q: float4-group in strip
        int t = t0 - 64 + q * 4;
        float4 v = make_float4(0.f, 0.f, 0.f, 0.f);
        if (t >= 0) v = *reinterpret_cast<const float4*>(uh + (size_t)b * bstr + t);
        uint32_t h0 = pk_bf2f(v.x, v.y), h1 = pk_bf2f(v.z, v.w);
        uint32_t g0 = pk_bf2f(v.x - bflo(h0), v.y - bfhi(h0));
        uint32_t g1 = pk_bf2f(v.z - bflo(h1), v.w - bfhi(h1));
        *reinterpret_cast<uint2*>(sBh + b * STRW + q * 2) = make_uint2(h0, h1);
        *reinterpret_cast<uint2*>(sBl + b * STRW + q * 2) = make_uint2(g0, g1);
    }
    __syncthreads();

    // Banded GEMM: warp wid -> row block jb; 4 tiles x 8 batches
    const int jb = wid;
    const int bb = lane >> 2;
    const int wq = lane & 3;
    float acc[NTILE][4];
    #pragma unroll
    for (int tl = 0; tl < NTILE; ++tl)
        #pragma unroll
        for (int q = 0; q < 4; ++q) acc[tl][q] = 0.0f;

    #pragma unroll
    for (int d = 0; d < 5; ++d) {
        const int w = (jb + d) * 8 + wq;
        #pragma unroll
        for (int tl = 0; tl < NTILE; ++tl) {
            const uint32_t* p = sBh + bb * STRW + tl * 64 + w;
            uint32_t b0h = p[0], b1h = p[4];
            uint32_t b0l = p[8 * STRW], b1l = p[8 * STRW + 4];
            mma_bf16(acc[tl], ah[d], b0h, b1h);
            mma_bf16(acc[tl], ah[d], b0l, b1l);
            mma_bf16(acc[tl], al[d], b0h, b1h);
        }
    }

    // Epilogue: transpose-stage through smem (reuse strips), coalesced STG
    __syncthreads();
    float* sO = reinterpret_cast<float*>(sBuf);        // 32 x OSTR
    {
        const int j  = jb * 16 + (lane >> 2);
        const int nn = (lane & 3) * 2;
        #pragma unroll
        for (int tl = 0; tl < NTILE; ++tl) {
            float* rp = sO + (size_t)(tl * 8 + nn) * OSTR;
            rp[j]            = acc[tl][0];
            rp[OSTR + j]     = acc[tl][1];
            rp[j + 8]        = acc[tl][2];
            rp[OSTR + j + 8] = acc[tl][3];
        }
    }
    __syncthreads();

    #pragma unroll
    for (int it = 0; it < 4; ++it) {
        int idx = tid + it * NT;                       // < 1024 float4 groups
        int n = idx >> 5, g = idx & 31;
        float4 v = *reinterpret_cast<float4*>(&sO[(size_t)n * OSTR + g * 4]);
        int tl = n >> 3, b = n & 7;
        *reinterpret_cast<float4*>(yh + (size_t)b * bstr + t0 + tl * 128 + g * 4) = v;
    }
}

extern "C" void kernel_launch(void* const* d_in, const int* in_sizes, int n_in,
                              void* d_out, int out_size) {
    const float* u = (const float*)d_in[0];   // (8, 512, 4096)
    const float* B = (const float*)d_in[1];   // (512, 64)
    const float* C = (const float*)d_in[2];   // (1, 512, 64)
    const float* D = (const float*)d_in[3];   // (512,)
    float* y = (float*)d_out;                 // (8, 512, 4096)

    prep_k<<<HCH, 192>>>(B, C, D);
    dim3 grid(LSEQ / TCTA, HCH);              // (8, 512) = 4096 CTAs
    conv_mma<<<grid, NT>>>(u, y);
}

// round 7
// speedup vs baseline: 1.4235x; 1.4235x over previous
#include <cuda_runtime.h>
#include <cuda_fp16.h>
#include <cstdint>

#define HCH  512
#define LSEQ 4096
#define TAPS 64

#define NT    256               // 8 warps
#define TCTA  256               // 2 seq-tiles of 128 per CTA
#define STRW  164               // u32 words per batch strip (160 used + 4 pad), 164%32==4
#define OSTR  132               // floats per output staging row

// Pre-packed fp16 A fragments: [h][d][word0..2][lane]
__device__ uint32_t g_ktab[HCH * 5 * 3 * 32];

__device__ __forceinline__ uint32_t pk_h2(float a, float b) {
    __half2 t = __floats2half2_rn(a, b);
    return *reinterpret_cast<uint32_t*>(&t);
}

__device__ __forceinline__ void mma_f16(float* d, const uint32_t* a,
                                        uint32_t b0, uint32_t b1) {
    asm volatile(
        "mma.sync.aligned.m16n8k16.row.col.f32.f16.f16.f32 "
        "{%0,%1,%2,%3}, {%4,%5,%6,%7}, {%8,%9}, {%0,%1,%2,%3};"
        : "+f"(d[0]), "+f"(d[1]), "+f"(d[2]), "+f"(d[3])
        : "r"(a[0]), "r"(a[1]), "r"(a[2]), "r"(a[3]), "r"(b0), "r"(b1));
}

// ---- prep: K[h,s] = sum_j B[h,j]*C[h,j+s] (+D at s=0); pack fp16 A-frag table ----
__global__ __launch_bounds__(160) void prep_k(const float* __restrict__ Bp,
                                              const float* __restrict__ Cp,
                                              const float* __restrict__ Dp) {
    __shared__ float sK[TAPS];
    const int h = blockIdx.x;
    const int tid = threadIdx.x;
    if (tid < TAPS) {
        const float* Bh = Bp + h * TAPS;
        const float* Ch = Cp + h * TAPS;
        float a = (tid == 0) ? Dp[h] : 0.0f;
        #pragma unroll
        for (int j = 0; j < TAPS; ++j)
            if (j + tid < TAPS) a = fmaf(Bh[j], Ch[j + tid], a);
        sK[tid] = a;
    }
    __syncthreads();
    {
        const int d = tid >> 5, lane = tid & 31;
        const int r = lane >> 2, c0 = (lane & 3) * 2;
        const int s0 = 64 - 16 * d + r - c0;
        const int ss[6] = { s0 + 8, s0 + 7, s0, s0 - 1, s0 - 8, s0 - 9 };
        float f[6];
        #pragma unroll
        for (int q = 0; q < 6; ++q)
            f[q] = (ss[q] >= 0 && ss[q] < TAPS) ? sK[ss[q]] : 0.0f;
        uint32_t* kt = g_ktab + (size_t)((h * 5 + d) * 3) * 32 + lane;
        kt[0]  = pk_h2(f[2], f[3]);   // a0: (r, c0),(r, c0+1)
        kt[32] = pk_h2(f[0], f[1]);   // a1: (r+8, ...)
        kt[64] = pk_h2(f[4], f[5]);   // a2: (r, c0+8...)
    }
}

// ---- conv: banded Toeplitz GEMM, 2 seq-tiles x 8 batches per CTA ----
__global__ __launch_bounds__(NT) void conv_mma(const float* __restrict__ up,
                                               float* __restrict__ yp) {
    __shared__ alignas(16) uint32_t sBuf[2 * 8 * STRW];   // hi strips | lo strips

    const int tid  = threadIdx.x;
    const int wid  = tid >> 5;
    const int lane = tid & 31;
    const int h    = blockIdx.y;
    const int t0   = blockIdx.x * TCTA;

    const float* uh = up + (size_t)h * LSEQ;
    float*       yh = yp + (size_t)h * LSEQ;
    const size_t bstr = (size_t)HCH * LSEQ;

    // A fragments from the prepacked table (coalesced LDG; L2-shared across 16 CTAs/h)
    uint32_t ah[5][4];
    #pragma unroll
    for (int d = 0; d < 5; ++d) {
        const uint32_t* kt = g_ktab + (size_t)((h * 5 + d) * 3) * 32 + lane;
        uint32_t w0 = kt[0], w1 = kt[32], w2 = kt[64];
        ah[d][0] = w0; ah[d][1] = w1; ah[d][2] = w2; ah[d][3] = w0;
    }

    // im2col: 8 batch strips, t in [t0-64, t0+256): 320 floats each, loaded once
    uint32_t* sBh = sBuf;
    uint32_t* sBl = sBuf + 8 * STRW;
    #pragma unroll
    for (int it = 0; it < 3; ++it) {
        int idx = tid + it * NT;
        if (idx < 640) {
            int b = idx / 80, q = idx - b * 80;        // q: float4-group in strip
            int t = t0 - 64 + q * 4;
            float4 v = make_float4(0.f, 0.f, 0.f, 0.f);
            if (t >= 0) v = *reinterpret_cast<const float4*>(uh + (size_t)b * bstr + t);
            uint32_t h0 = pk_h2(v.x, v.y), h1 = pk_h2(v.z, v.w);
            float2 f0 = __half22float2(*reinterpret_cast<__half2*>(&h0));
            float2 f1 = __half22float2(*reinterpret_cast<__half2*>(&h1));
            uint32_t l0 = pk_h2(v.x - f0.x, v.y - f0.y);
            uint32_t l1 = pk_h2(v.z - f1.x, v.w - f1.y);
            *reinterpret_cast<uint2*>(sBh + b * STRW + q * 2) = make_uint2(h0, h1);
            *reinterpret_cast<uint2*>(sBl + b * STRW + q * 2) = make_uint2(l0, l1);
        }
    }
    __syncthreads();

    // Banded GEMM: warp wid -> row block jb; 2 tiles x 8 batches, fp16 2-product
    const int jb = wid;
    const int bb = lane >> 2;
    const int wq = lane & 3;
    float acc[2][4];
    #pragma unroll
    for (int tl = 0; tl < 2; ++tl)
        #pragma unroll
        for (int q = 0; q < 4; ++q) acc[tl][q] = 0.0f;

    #pragma unroll
    for (int d = 0; d < 5; ++d) {
        const int w = (jb + d) * 8 + wq;
        #pragma unroll
        for (int tl = 0; tl < 2; ++tl) {
            const uint32_t* p = sBh + bb * STRW + tl * 64 + w;
            uint32_t b0h = p[0], b1h = p[4];
            uint32_t b0l = p[8 * STRW], b1l = p[8 * STRW + 4];
            mma_f16(acc[tl], ah[d], b0h, b1h);
            mma_f16(acc[tl], ah[d], b0l, b1l);
        }
    }

    // Epilogue: stage D frags to smem (conflict-free), coalesced float4 STG
    __syncthreads();
    float* sO = reinterpret_cast<float*>(sBuf);        // 16 x OSTR floats
    {
        const int j  = jb * 16 + (lane >> 2);
        const int nn = (lane & 3) * 2;
        #pragma unroll
        for (int tl = 0; tl < 2; ++tl) {
            float* rp = sO + (size_t)(tl * 8 + nn) * OSTR;
            rp[j]            = acc[tl][0];
            rp[OSTR + j]     = acc[tl][1];
            rp[j + 8]        = acc[tl][2];
            rp[OSTR + j + 8] = acc[tl][3];
        }
    }
    __syncthreads();

    #pragma unroll
    for (int it = 0; it < 2; ++it) {
        int idx = tid + it * NT;                       // < 512 float4 groups
        int n = idx >> 5, g = idx & 31;
        float4 v = *reinterpret_cast<float4*>(&sO[(size_t)n * OSTR + g * 4]);
        int tl = n >> 3, b = n & 7;
        *reinterpret_cast<float4*>(yh + (size_t)b * bstr + t0 + tl * 128 + g * 4) = v;
    }
}

extern "C" void kernel_launch(void* const* d_in, const int* in_sizes, int n_in,
                              void* d_out, int out_size) {
    const float* u = (const float*)d_in[0];   // (8, 512, 4096)
    const float* B = (const float*)d_in[1];   // (512, 64)
    const float* C = (const float*)d_in[2];   // (1, 512, 64)
    const float* D = (const float*)d_in[3];   // (512,)
    float* y = (float*)d_out;                 // (8, 512, 4096)

    prep_k<<<HCH, 160>>>(B, C, D);
    dim3 grid(LSEQ / TCTA, HCH);              // (16, 512) = 8192 CTAs
    conv_mma<<<grid, NT>>>(u, y);
}

// round 8
// speedup vs baseline: 1.4950x; 1.0502x over previous
#include <cuda_runtime.h>
#include <cuda_fp16.h>
#include <cstdint>

#define HCH  512
#define LSEQ 4096
#define TAPS 64

#define NT    256               // 8 warps
#define TCTA  256               // 2 seq-tiles of 128 per CTA
#define STRW  164               // u32 words per batch strip (160 used + 4 pad)
#define OSTR  132               // floats per output staging row

__device__ __forceinline__ uint32_t pk_h2(float a, float b) {
    __half2 t = __floats2half2_rn(a, b);
    return *reinterpret_cast<uint32_t*>(&t);
}
__device__ __forceinline__ uint32_t smem_u32(const void* p) {
    uint32_t a;
    asm("{ .reg .u64 t; cvta.to.shared.u64 t, %1; cvt.u32.u64 %0, t; }" : "=r"(a) : "l"(p));
    return a;
}
__device__ __forceinline__ void mma_f16(float* d, uint32_t a0, uint32_t a1,
                                        uint32_t a2, uint32_t a3,
                                        uint32_t b0, uint32_t b1) {
    asm volatile(
        "mma.sync.aligned.m16n8k16.row.col.f32.f16.f16.f32 "
        "{%0,%1,%2,%3}, {%4,%5,%6,%7}, {%8,%9}, {%0,%1,%2,%3};"
        : "+f"(d[0]), "+f"(d[1]), "+f"(d[2]), "+f"(d[3])
        : "r"(a0), "r"(a1), "r"(a2), "r"(a3), "r"(b0), "r"(b1));
}
__device__ __forceinline__ void ldsm_x4(uint32_t& r0, uint32_t& r1,
                                        uint32_t& r2, uint32_t& r3, uint32_t addr) {
    asm volatile("ldmatrix.sync.aligned.m8n8.x4.shared.b16 {%0,%1,%2,%3}, [%4];"
                 : "=r"(r0), "=r"(r1), "=r"(r2), "=r"(r3) : "r"(addr));
}

__global__ __launch_bounds__(NT) void conv_mma(const float* __restrict__ up,
                                               const float* __restrict__ Bp,
                                               const float* __restrict__ Cp,
                                               const float* __restrict__ Dp,
                                               float* __restrict__ yp) {
    __shared__ alignas(16) uint32_t sBuf[2 * 8 * STRW];   // hi strips | lo strips
    __shared__ float sK[TAPS];

    const int tid  = threadIdx.x;
    const int wid  = tid >> 5;
    const int lane = tid & 31;
    const int h    = blockIdx.y;
    const int t0   = blockIdx.x * TCTA;

    const float* uh = up + (size_t)h * LSEQ;
    float*       yh = yp + (size_t)h * LSEQ;
    const size_t bstr = (size_t)HCH * LSEQ;

    // ---- warps 0-1: K[h,s] = sum_j B[h,j]*C[h,j+s] (+D at s=0) ----
    if (tid < TAPS) {
        const float* Bh = Bp + h * TAPS;
        const float* Ch = Cp + h * TAPS;
        float a = (tid == 0) ? Dp[h] : 0.0f;
        #pragma unroll
        for (int j = 0; j < TAPS; ++j)
            if (j + tid < TAPS) a = fmaf(Bh[j], Ch[j + tid], a);
        sK[tid] = a;
    }

    // ---- warps 2-7: im2col, 8 batch strips, t in [t0-64, t0+256), hi/lo fp16 ----
    uint32_t* sBh = sBuf;
    uint32_t* sBl = sBuf + 8 * STRW;
    if (tid >= 64) {
        #pragma unroll
        for (int it = 0; it < 4; ++it) {
            int idx = (tid - 64) + it * 192;
            if (idx < 640) {
                int b = idx / 80, q = idx - b * 80;      // q: float4-group in strip
                int t = t0 - 64 + q * 4;
                float4 v = make_float4(0.f, 0.f, 0.f, 0.f);
                if (t >= 0) v = *reinterpret_cast<const float4*>(uh + (size_t)b * bstr + t);
                uint32_t h0 = pk_h2(v.x, v.y), h1 = pk_h2(v.z, v.w);
                float2 f0 = __half22float2(*reinterpret_cast<__half2*>(&h0));
                float2 f1 = __half22float2(*reinterpret_cast<__half2*>(&h1));
                uint32_t l0 = pk_h2(v.x - f0.x, v.y - f0.y);
                uint32_t l1 = pk_h2(v.z - f1.x, v.w - f1.y);
                *reinterpret_cast<uint2*>(sBh + b * STRW + q * 2) = make_uint2(h0, h1);
                *reinterpret_cast<uint2*>(sBl + b * STRW + q * 2) = make_uint2(l0, l1);
            }
        }
    }
    __syncthreads();

    // ---- per-warp A fragments from sK: A[m,k] = K[64 + m - k - 16d] ----
    uint32_t fh[5][3];
    {
        const int r  = lane >> 2;
        const int c0 = (lane & 3) * 2;
        #pragma unroll
        for (int d = 0; d < 5; ++d) {
            const int s0 = 64 - 16 * d + r - c0;
            const int ss[6] = { s0 + 8, s0 + 7, s0, s0 - 1, s0 - 8, s0 - 9 };
            float f[6];
            #pragma unroll
            for (int q = 0; q < 6; ++q)
                f[q] = ((unsigned)ss[q] < TAPS) ? sK[ss[q]] : 0.0f;
            fh[d][0] = pk_h2(f[2], f[3]);    // a0: (r, c0),(r, c0+1)   (a3 == a0)
            fh[d][1] = pk_h2(f[0], f[1]);    // a1: (r+8, ...)
            fh[d][2] = pk_h2(f[4], f[5]);    // a2: (r, c0+8...)
        }
    }

    // ---- Banded GEMM: warp wid -> row block jb; ldmatrix.x4 B loads ----
    const int jb = wid;
    // per-lane ldmatrix row base: lanes 0-7 -> hi k0-7, 8-15 -> hi k8-15,
    //                             16-23 -> lo k0-7, 24-31 -> lo k8-15
    const uint32_t ldm_base = smem_u32(sBuf) +
        (((lane & 7) * STRW) + (((lane >> 4) & 1) * 8 * STRW) + (((lane >> 3) & 1) * 4)) * 4;

    float acc[2][4];
    #pragma unroll
    for (int tl = 0; tl < 2; ++tl)
        #pragma unroll
        for (int q = 0; q < 4; ++q) acc[tl][q] = 0.0f;

    #pragma unroll
    for (int d = 0; d < 5; ++d) {
        #pragma unroll
        for (int tl = 0; tl < 2; ++tl) {
            uint32_t b0h, b1h, b0l, b1l;
            ldsm_x4(b0h, b1h, b0l, b1l, ldm_base + ((jb + d) * 8 + tl * 64) * 4);
            mma_f16(acc[tl], fh[d][0], fh[d][1], fh[d][2], fh[d][0], b0h, b1h);
            mma_f16(acc[tl], fh[d][0], fh[d][1], fh[d][2], fh[d][0], b0l, b1l);
        }
    }

    // ---- Epilogue: stage D frags to smem (conflict-free), coalesced float4 STG ----
    __syncthreads();
    float* sO = reinterpret_cast<float*>(sBuf);          // 16 x OSTR floats
    {
        const int j  = jb * 16 + (lane >> 2);
        const int nn = (lane & 3) * 2;
        #pragma unroll
        for (int tl = 0; tl < 2; ++tl) {
            float* rp = sO + (size_t)(tl * 8 + nn) * OSTR;
            rp[j]            = acc[tl][0];
            rp[OSTR + j]     = acc[tl][1];
            rp[j + 8]        = acc[tl][2];
            rp[OSTR + j + 8] = acc[tl][3];
        }
    }
    __syncthreads();

    #pragma unroll
    for (int it = 0; it < 2; ++it) {
        int idx = tid + it * NT;                         // < 512 float4 groups
        int n = idx >> 5, g = idx & 31;
        float4 v = *reinterpret_cast<float4*>(&sO[(size_t)n * OSTR + g * 4]);
        int tl = n >> 3, b = n & 7;
        *reinterpret_cast<float4*>(yh + (size_t)b * bstr + t0 + tl * 128 + g * 4) = v;
    }
}

extern "C" void kernel_launch(void* const* d_in, const int* in_sizes, int n_in,
                              void* d_out, int out_size) {
    const float* u = (const float*)d_in[0];   // (8, 512, 4096)
    const float* B = (const float*)d_in[1];   // (512, 64)
    const float* C = (const float*)d_in[2];   // (1, 512, 64)
    const float* D = (const float*)d_in[3];   // (512,)
    float* y = (float*)d_out;                 // (8, 512, 4096)

    dim3 grid(LSEQ / TCTA, HCH);              // (16, 512) = 8192 CTAs
    conv_mma<<<grid, NT>>>(u, B, C, D, y);
}

// round 9
// speedup vs baseline: 1.5626x; 1.0452x over previous
#include <cuda_runtime.h>
#include <cuda_fp16.h>
#include <cstdint>

#define HCH  512
#define LSEQ 4096
#define TAPS 64

#define NT    256               // 8 warps
#define TCTA  256               // 2 seq-tiles of 128 per CTA
#define STRW  164               // u32 words per batch strip (160 used + 4 pad)
#define OSTR  132               // floats per output staging row

__device__ __forceinline__ uint32_t pk_h2(float a, float b) {
    __half2 t = __floats2half2_rn(a, b);
    return *reinterpret_cast<uint32_t*>(&t);
}
__device__ __forceinline__ uint32_t smem_u32(const void* p) {
    uint32_t a;
    asm("{ .reg .u64 t; cvta.to.shared.u64 t, %1; cvt.u32.u64 %0, t; }" : "=r"(a) : "l"(p));
    return a;
}
__device__ __forceinline__ void mma_f16(float* d, uint32_t a0, uint32_t a1,
                                        uint32_t a2, uint32_t a3,
                                        uint32_t b0, uint32_t b1) {
    asm volatile(
        "mma.sync.aligned.m16n8k16.row.col.f32.f16.f16.f32 "
        "{%0,%1,%2,%3}, {%4,%5,%6,%7}, {%8,%9}, {%0,%1,%2,%3};"
        : "+f"(d[0]), "+f"(d[1]), "+f"(d[2]), "+f"(d[3])
        : "r"(a0), "r"(a1), "r"(a2), "r"(a3), "r"(b0), "r"(b1));
}
__device__ __forceinline__ void ldsm_x4(uint32_t& r0, uint32_t& r1,
                                        uint32_t& r2, uint32_t& r3, uint32_t addr) {
    asm volatile("ldmatrix.sync.aligned.m8n8.x4.shared.b16 {%0,%1,%2,%3}, [%4];"
                 : "=r"(r0), "=r"(r1), "=r"(r2), "=r"(r3) : "r"(addr));
}

__global__ __launch_bounds__(NT) void conv_mma(const float* __restrict__ up,
                                               const float* __restrict__ Bp,
                                               const float* __restrict__ Cp,
                                               const float* __restrict__ Dp,
                                               float* __restrict__ yp) {
    __shared__ alignas(16) uint32_t sBuf[8 * STRW];   // 8 fp16-hi batch strips
    __shared__ float    sK[TAPS];
    __shared__ uint32_t sTab[5 * 3 * 32];             // A-frag words [d][w][lane]
    __shared__ float    sO[16 * OSTR];                // output staging

    const int tid  = threadIdx.x;
    const int wid  = tid >> 5;
    const int lane = tid & 31;
    const int h    = blockIdx.y;
    const int t0   = blockIdx.x * TCTA;

    const float* uh = up + (size_t)h * LSEQ;
    float*       yh = yp + (size_t)h * LSEQ;
    const size_t bstr = (size_t)HCH * LSEQ;

    if (tid < 64) {
        // ---- warps 0-1: K[h,s] = sum_j B[h,j]*C[h,j+s] (+D at s=0) ----
        {
            const float* Bh = Bp + h * TAPS;
            const float* Ch = Cp + h * TAPS;
            float a = (tid == 0) ? Dp[h] : 0.0f;
            #pragma unroll
            for (int j = 0; j < TAPS; ++j)
                if (j + tid < TAPS) a = fmaf(Bh[j], Ch[j + tid], a);
            sK[tid] = a;
        }
        asm volatile("bar.sync 1, 64;" ::: "memory");   // warps 0-1 only

        // ---- build A-frag table (480 words, warp-invariant) ----
        // word(widx): lane l, dw = widx>>5, d = dw/3, w = dw%3
        //   s0 = 64 - 16d + (l>>2) - 2(l&3)
        //   w0 -> (s0, s0-1), w1 -> (s0+8, s0+7), w2 -> (s0-8, s0-9)
        #pragma unroll
        for (int it = 0; it < 8; ++it) {
            int widx = tid + it * 64;
            if (widx < 480) {
                int l = widx & 31, dw = widx >> 5;
                int d = dw / 3, w = dw - d * 3;
                int s0 = 64 - 16 * d + (l >> 2) - ((l & 3) << 1);
                int sa = s0 + ((w == 1) ? 8 : (w == 2) ? -8 : 0);
                float fa = ((unsigned)sa < TAPS) ? sK[sa] : 0.0f;
                float fb = ((unsigned)(sa - 1) < TAPS) ? sK[sa - 1] : 0.0f;
                sTab[widx] = pk_h2(fa, fb);
            }
        }
    } else {
        // ---- warps 2-7: im2col, 8 strips of 320 floats, t in [t0-64, t0+256) ----
        #pragma unroll
        for (int it = 0; it < 2; ++it) {
            int idx = (tid - 64) + it * 192;            // 8-float group index
            if (idx < 320) {
                int b = idx / 40, q8 = idx - b * 40;
                int t = t0 - 64 + q8 * 8;
                float4 v0 = make_float4(0.f, 0.f, 0.f, 0.f);
                float4 v1 = v0;
                if (t >= 0) {
                    const float* p = uh + (size_t)b * bstr + t;
                    v0 = *reinterpret_cast<const float4*>(p);
                    v1 = *reinterpret_cast<const float4*>(p + 4);
                }
                uint4 w;
                w.x = pk_h2(v0.x, v0.y); w.y = pk_h2(v0.z, v0.w);
                w.z = pk_h2(v1.x, v1.y); w.w = pk_h2(v1.z, v1.w);
                *reinterpret_cast<uint4*>(sBuf + b * STRW + q8 * 4) = w;
            }
        }
    }
    __syncthreads();

    // ---- per-warp A fragments: 15 coalesced conflict-free LDS.32 ----
    uint32_t fh[5][3];
    #pragma unroll
    for (int d = 0; d < 5; ++d)
        #pragma unroll
        for (int w = 0; w < 3; ++w)
            fh[d][w] = sTab[(d * 3 + w) * 32 + lane];

    // ---- Banded GEMM: warp wid -> row block jb ----
    // ldmatrix.x4 per d: matrices {tl0:k0-7, tl0:k8-15, tl1:k0-7, tl1:k8-15}
    const int jb = wid;
    const uint32_t ldm_base = smem_u32(sBuf) +
        (((lane & 7) * STRW) + (((lane >> 3) & 1) * 4) + (((lane >> 4) & 1) * 64)) * 4;

    float acc[2][4];
    #pragma unroll
    for (int tl = 0; tl < 2; ++tl)
        #pragma unroll
        for (int q = 0; q < 4; ++q) acc[tl][q] = 0.0f;

    #pragma unroll
    for (int d = 0; d < 5; ++d) {
        uint32_t b00, b01, b10, b11;
        ldsm_x4(b00, b01, b10, b11, ldm_base + (jb + d) * 32);   // 8 words * 4B
        mma_f16(acc[0], fh[d][0], fh[d][1], fh[d][2], fh[d][0], b00, b01);
        mma_f16(acc[1], fh[d][0], fh[d][1], fh[d][2], fh[d][0], b10, b11);
    }

    // ---- Epilogue: stage D frags (conflict-free), coalesced float4 STG ----
    {
        const int j  = jb * 16 + (lane >> 2);
        const int nn = (lane & 3) * 2;
        #pragma unroll
        for (int tl = 0; tl < 2; ++tl) {
            float* rp = sO + (size_t)(tl * 8 + nn) * OSTR;
            rp[j]            = acc[tl][0];
            rp[OSTR + j]     = acc[tl][1];
            rp[j + 8]        = acc[tl][2];
            rp[OSTR + j + 8] = acc[tl][3];
        }
    }
    __syncthreads();

    #pragma unroll
    for (int it = 0; it < 2; ++it) {
        int idx = tid + it * NT;                         // < 512 float4 groups
        int n = idx >> 5, g = idx & 31;
        float4 v = *reinterpret_cast<float4*>(&sO[(size_t)n * OSTR + g * 4]);
        int tl = n >> 3, b = n & 7;
        *reinterpret_cast<float4*>(yh + (size_t)b * bstr + t0 + tl * 128 + g * 4) = v;
    }
}

extern "C" void kernel_launch(void* const* d_in, const int* in_sizes, int n_in,
                              void* d_out, int out_size) {
    const float* u = (const float*)d_in[0];   // (8, 512, 4096)
    const float* B = (const float*)d_in[1];   // (512, 64)
    const float* C = (const float*)d_in[2];   // (1, 512, 64)
    const float* D = (const float*)d_in[3];   // (512,)
    float* y = (float*)d_out;                 // (8, 512, 4096)

    dim3 grid(LSEQ / TCTA, HCH);              // (16, 512) = 8192 CTAs
    conv_mma<<<grid, NT>>>(u, B, C, D, y);
}

// round 10
// speedup vs baseline: 1.6477x; 1.0545x over previous
#include <cuda_runtime.h>
#include <cuda_fp16.h>
#include <cstdint>

#define HCH  512
#define LSEQ 4096
#define TAPS 64

#define NT    256               // 8 warps
#define NTILE 4
#define TCTA  512               // 4 seq-tiles of 128 per CTA
#define STRW  292               // u32 words per batch strip (288 used + 4 pad), 292%32==4

// Pre-packed fp16 A fragments: [h][d*3+w][lane]
__device__ uint32_t g_ktab[HCH * 15 * 32];

__device__ __forceinline__ uint32_t pk_h2(float a, float b) {
    __half2 t = __floats2half2_rn(a, b);
    return *reinterpret_cast<uint32_t*>(&t);
}
__device__ __forceinline__ uint32_t smem_u32(const void* p) {
    uint32_t a;
    asm("{ .reg .u64 t; cvta.to.shared.u64 t, %1; cvt.u32.u64 %0, t; }" : "=r"(a) : "l"(p));
    return a;
}
__device__ __forceinline__ void mma_f16(float* d, uint32_t a0, uint32_t a1,
                                        uint32_t a2, uint32_t a3,
                                        uint32_t b0, uint32_t b1) {
    asm volatile(
        "mma.sync.aligned.m16n8k16.row.col.f32.f16.f16.f32 "
        "{%0,%1,%2,%3}, {%4,%5,%6,%7}, {%8,%9}, {%0,%1,%2,%3};"
        : "+f"(d[0]), "+f"(d[1]), "+f"(d[2]), "+f"(d[3])
        : "r"(a0), "r"(a1), "r"(a2), "r"(a3), "r"(b0), "r"(b1));
}
__device__ __forceinline__ void ldsm_x4(uint32_t& r0, uint32_t& r1,
                                        uint32_t& r2, uint32_t& r3, uint32_t addr) {
    asm volatile("ldmatrix.sync.aligned.m8n8.x4.shared.b16 {%0,%1,%2,%3}, [%4];"
                 : "=r"(r0), "=r"(r1), "=r"(r2), "=r"(r3) : "r"(addr));
}

// ---- prep: K[h,s] = sum_j B[h,j]*C[h,j+s] (+D at s=0); pack fp16 A-frag table ----
__global__ __launch_bounds__(160) void prep_k(const float* __restrict__ Bp,
                                              const float* __restrict__ Cp,
                                              const float* __restrict__ Dp) {
    __shared__ float sK[TAPS];
    const int h = blockIdx.x;
    const int tid = threadIdx.x;
    if (tid < TAPS) {
        const float* Bh = Bp + h * TAPS;
        const float* Ch = Cp + h * TAPS;
        float a = (tid == 0) ? Dp[h] : 0.0f;
        #pragma unroll
        for (int j = 0; j < TAPS; ++j)
            if (j + tid < TAPS) a = fmaf(Bh[j], Ch[j + tid], a);
        sK[tid] = a;
    }
    __syncthreads();
    {
        const int d = tid >> 5, lane = tid & 31;         // d = 0..4
        const int s0 = 64 - 16 * d + (lane >> 2) - ((lane & 3) << 1);
        uint32_t* kt = g_ktab + ((size_t)h * 15 + d * 3) * 32 + lane;
        #pragma unroll
        for (int w = 0; w < 3; ++w) {
            int sa = s0 + ((w == 1) ? 8 : (w == 2) ? -8 : 0);
            float fa = ((unsigned)sa < TAPS) ? sK[sa] : 0.0f;
            float fb = ((unsigned)(sa - 1) < TAPS) ? sK[sa - 1] : 0.0f;
            kt[w * 32] = pk_h2(fa, fb);                  // w0:(s0,s0-1) w1:(+8) w2:(-8)
        }
    }
}

// ---- conv: banded Toeplitz GEMM, 4 seq-tiles x 8 batches per CTA ----
__global__ __launch_bounds__(NT, 4) void conv_mma(const float* __restrict__ up,
                                                  float* __restrict__ yp) {
    __shared__ alignas(16) uint32_t sBuf[8 * STRW];      // 8 fp16 batch strips

    const int tid  = threadIdx.x;
    const int wid  = tid >> 5;
    const int lane = tid & 31;
    const int h    = blockIdx.y;
    const int t0   = blockIdx.x * TCTA;

    const float* uh = up + (size_t)h * LSEQ;
    float*       yh = yp + (size_t)h * LSEQ;
    const size_t bstr = (size_t)HCH * LSEQ;

    // A fragments: 15 coalesced LDG.32 (L2-shared across CTAs of this channel)
    uint32_t fh[5][3];
    {
        const uint32_t* kt = g_ktab + (size_t)h * 15 * 32 + lane;
        #pragma unroll
        for (int d = 0; d < 5; ++d)
            #pragma unroll
            for (int w = 0; w < 3; ++w)
                fh[d][w] = kt[(d * 3 + w) * 32];
    }

    // im2col: 8 strips of 576 floats (t in [t0-64, t0+512)), each element once
    #pragma unroll
    for (int it = 0; it < 3; ++it) {
        int idx = tid + it * NT;                         // 8-float group index
        if (idx < 576) {
            int b = idx / 72, q8 = idx - b * 72;
            int t = t0 - 64 + q8 * 8;
            float4 v0 = make_float4(0.f, 0.f, 0.f, 0.f);
            float4 v1 = v0;
            if (t >= 0) {
                const float* p = uh + (size_t)b * bstr + t;
                v0 = *reinterpret_cast<const float4*>(p);
                v1 = *reinterpret_cast<const float4*>(p + 4);
            }
            uint4 w;
            w.x = pk_h2(v0.x, v0.y); w.y = pk_h2(v0.z, v0.w);
            w.z = pk_h2(v1.x, v1.y); w.w = pk_h2(v1.z, v1.w);
            *reinterpret_cast<uint4*>(sBuf + b * STRW + q8 * 4) = w;
        }
    }
    __syncthreads();

    // Banded GEMM: warp wid -> row block jb; ldmatrix.x4 covers 2 tiles per load
    const int jb = wid;
    const uint32_t ldm_base = smem_u32(sBuf) +
        (((lane & 7) * STRW) + (((lane >> 3) & 1) * 4) + (((lane >> 4) & 1) * 64)) * 4;

    float acc[NTILE][4];
    #pragma unroll
    for (int tl = 0; tl < NTILE; ++tl)
        #pragma unroll
        for (int q = 0; q < 4; ++q) acc[tl][q] = 0.0f;

    #pragma unroll
    for (int d = 0; d < 5; ++d) {
        #pragma unroll
        for (int tp = 0; tp < 2; ++tp) {                 // tile pairs (0,1) and (2,3)
            uint32_t b00, b01, b10, b11;
            ldsm_x4(b00, b01, b10, b11, ldm_base + ((jb + d) * 8 + tp * 128) * 4);
            mma_f16(acc[2 * tp],     fh[d][0], fh[d][1], fh[d][2], fh[d][0], b00, b01);
            mma_f16(acc[2 * tp + 1], fh[d][0], fh[d][1], fh[d][2], fh[d][0], b10, b11);
        }
    }

    // Direct epilogue: lane owns (j, j+8) x (b, b+1) per tile
    {
        const int j  = jb * 16 + (lane >> 2);
        const int nn = (lane & 3) * 2;
        float* p0 = yh + (size_t)nn * bstr + t0 + j;
        #pragma unroll
        for (int tl = 0; tl < NTILE; ++tl) {
            float* q0 = p0 + tl * 128;
            float* q1 = q0 + bstr;
            q0[0] = acc[tl][0];
            q1[0] = acc[tl][1];
            q0[8] = acc[tl][2];
            q1[8] = acc[tl][3];
        }
    }
}

extern "C" void kernel_launch(void* const* d_in, const int* in_sizes, int n_in,
                              void* d_out, int out_size) {
    const float* u = (const float*)d_in[0];   // (8, 512, 4096)
    const float* B = (const float*)d_in[1];   // (512, 64)
    const float* C = (const float*)d_in[2];   // (1, 512, 64)
    const float* D = (const float*)d_in[3];   // (512,)
    float* y = (float*)d_out;                 // (8, 512, 4096)

    prep_k<<<HCH, 160>>>(B, C, D);
    dim3 grid(LSEQ / TCTA, HCH);              // (8, 512) = 4096 CTAs
    conv_mma<<<grid, NT>>>(u, y);
}